// round 13
// baseline (speedup 1.0000x reference)
#include <cuda_runtime.h>

#define H    16
#define NBOX 128
#define DIN  256
#define DKD  128
#define DG   64

typedef unsigned long long ull;

// Scratch (device globals — no allocations allowed)
__device__ float g_glog[H * NBOX * NBOX];      // log(clip(relu(gate))): 1 MB
__device__ float g_qkv[3 * H * NBOX * DKD];    // k,q,v projections: 3 MB
__device__ float g_partial[H * 4 * DKD];       // per-mtile partial colsums

// ---- packed f32x2 helpers (sm_10x FFMA2) ----------------------------------
__device__ __forceinline__ void fma2(ull& acc, ull a, ull b) {
    asm("fma.rn.f32x2 %0, %1, %2, %0;" : "+l"(acc) : "l"(a), "l"(b));
}
__device__ __forceinline__ ull dup2(float a) {
    ull r; asm("mov.b64 %0, {%1, %1};" : "=l"(r) : "f"(a)); return r;
}
__device__ __forceinline__ float2 unpack2(ull v) {
    float2 r; asm("mov.b64 {%0, %1}, %2;" : "=f"(r.x), "=f"(r.y) : "l"(v)); return r;
}

// Dynamic smem (proj):
//   AsT: 256 d x 128 rows f32 (transposed f_a)   = 131072 B
//   Ws2: 256 d x 32 ull (64 cols as f32x2 pairs) =  65536 B
#define DS_TOTAL   (256 * 128 * 4 + 256 * 32 * 8)   // 196608

// ---------------------------------------------------------------------------
// k_gate (standalone, 21 KB STATIC smem -> many blocks/SM, 1 wave):
//   glog[h,m,n] = log(max(pos[m,n,:]·WG[h]+bg[h],1e-6)); 64 pairs/block.
// ---------------------------------------------------------------------------
__global__ void __launch_bounds__(256) k_gate(
        const float* __restrict__ pos,
        const float* __restrict__ WG, const float* __restrict__ bg) {
    __shared__ __align__(16) float pos_s[64][65];
    __shared__ __align__(16) float wg_s[H * DG];

    int tid = threadIdx.x;
    int p0 = blockIdx.x * 64;   // pair base (pair = m*128+n)

    ((float4*)wg_s)[tid] = ((const float4*)WG)[tid];
#pragma unroll
    for (int it = 0; it < 4; ++it) {
        int fidx = tid + 256 * it;
        int pl = fidx >> 4, g4 = fidx & 15;
        float4 v = ((const float4*)pos)[(long)(p0 + pl) * 16 + g4];
        pos_s[pl][4 * g4 + 0] = v.x;
        pos_s[pl][4 * g4 + 1] = v.y;
        pos_s[pl][4 * g4 + 2] = v.z;
        pos_s[pl][4 * g4 + 3] = v.w;
    }
    __syncthreads();

    int row = tid & 63;
    int hg  = tid >> 6;       // heads {hg, hg+4, hg+8, hg+12}
    float acc[4] = {0.f, 0.f, 0.f, 0.f};
#pragma unroll
    for (int g = 0; g < DG; ++g) {
        float pv = pos_s[row][g];
#pragma unroll
        for (int j = 0; j < 4; ++j)
            acc[j] = fmaf(pv, wg_s[(hg + 4 * j) * DG + g], acc[j]);
    }
#pragma unroll
    for (int j = 0; j < 4; ++j) {
        int h = hg + 4 * j;
        float x = acc[j] + bg[h];
        g_glog[h * (NBOX * NBOX) + p0 + row] = __logf(fmaxf(x, 1e-6f));
    }
}

// ---------------------------------------------------------------------------
// k_proj (96 blocks, 256 threads, 192 KB dynamic smem, exactly 1 wave):
//   C(128 x 64) = f_a(128x256) @ W[h,p][:, c0..c0+64) + b
//   A (transposed) + W half-panel staged ONCE; ONE __syncthreads;
//   256-d loop: no barriers, no global loads.
//   warp = 16 rows x 64 cols (32*16+4*64=768 <= 1024 -> crossbar 75%).
// ---------------------------------------------------------------------------
__global__ void __launch_bounds__(256) k_proj(
        const float* __restrict__ f_a,
        const float* __restrict__ WK, const float* __restrict__ bk,
        const float* __restrict__ WQ, const float* __restrict__ bq,
        const float* __restrict__ WV, const float* __restrict__ bv) {
    extern __shared__ __align__(16) char dsm[];
    int tid = threadIdx.x;
    int w = tid >> 5, L = tid & 31;

    float (*AsT)[128] = (float(*)[128])dsm;                   // [d][row]
    ull   (*Ws2)[32]  = (ull(*)[32])(dsm + 256 * 128 * 4);    // [d][colpair]

    int bid = blockIdx.x;
    int ct = bid & 1;               // col half: cols 64ct .. 64ct+63
    int p  = (bid >> 1) % 3;
    int h  = bid / 6;
    const float* W  = (p == 0) ? WK : ((p == 1) ? WQ : WV);
    const float* bb = (p == 0) ? bk : ((p == 1) ? bq : bv);
    const float* Wh = W + (long)h * DIN * DKD;
    int c0 = 64 * ct;

    // ---- stage A transposed: lane = row (conflict-free STS) ----
#pragma unroll
    for (int it = 0; it < 32; ++it) {
        int idx = w + 8 * it;               // 0..255
        int c4 = idx & 63, rblk = idx >> 6;
        int r = 32 * rblk + L;
        float4 v = *(const float4*)&f_a[r * DIN + 4 * c4];
        AsT[4 * c4 + 0][r] = v.x;
        AsT[4 * c4 + 1][r] = v.y;
        AsT[4 * c4 + 2][r] = v.z;
        AsT[4 * c4 + 3][r] = v.w;
    }
    // ---- stage W half-panel: coalesced LDG.128 + STS.128 ----
#pragma unroll
    for (int it = 0; it < 16; ++it) {
        int fidx = tid + 256 * it;          // 0..4095
        int d = fidx >> 4, q = fidx & 15;
        ulonglong2 v = *(const ulonglong2*)&Wh[d * DKD + c0 + 4 * q];
        *(ulonglong2*)&Ws2[d][2 * q] = v;
    }
    __syncthreads();   // the ONLY barrier

    int r0 = 16 * w;                // warp rows 16w .. 16w+15 (8 ull pairs)
    ull acc[8][2] = {};             // [row-pair j][col i]

    // software-pipelined 256-d loop: zero barriers, zero global loads
    ulonglong2 a0 = *(ulonglong2*)&AsT[0][r0 + 0];
    ulonglong2 a1 = *(ulonglong2*)&AsT[0][r0 + 4];
    ulonglong2 a2 = *(ulonglong2*)&AsT[0][r0 + 8];
    ulonglong2 a3 = *(ulonglong2*)&AsT[0][r0 + 12];
    float2 wf = *(float2*)&Ws2[0][L];   // cols c0+2L, c0+2L+1

#pragma unroll 4
    for (int d = 0; d < DIN - 1; ++d) {
        ulonglong2 n0 = *(ulonglong2*)&AsT[d + 1][r0 + 0];
        ulonglong2 n1 = *(ulonglong2*)&AsT[d + 1][r0 + 4];
        ulonglong2 n2 = *(ulonglong2*)&AsT[d + 1][r0 + 8];
        ulonglong2 n3 = *(ulonglong2*)&AsT[d + 1][r0 + 12];
        float2 nw = *(float2*)&Ws2[d + 1][L];
        ull W0 = dup2(wf.x), W1 = dup2(wf.y);
        fma2(acc[0][0], a0.x, W0);  fma2(acc[0][1], a0.x, W1);
        fma2(acc[1][0], a0.y, W0);  fma2(acc[1][1], a0.y, W1);
        fma2(acc[2][0], a1.x, W0);  fma2(acc[2][1], a1.x, W1);
        fma2(acc[3][0], a1.y, W0);  fma2(acc[3][1], a1.y, W1);
        fma2(acc[4][0], a2.x, W0);  fma2(acc[4][1], a2.x, W1);
        fma2(acc[5][0], a2.y, W0);  fma2(acc[5][1], a2.y, W1);
        fma2(acc[6][0], a3.x, W0);  fma2(acc[6][1], a3.x, W1);
        fma2(acc[7][0], a3.y, W0);  fma2(acc[7][1], a3.y, W1);
        a0 = n0; a1 = n1; a2 = n2; a3 = n3; wf = nw;
    }
    {   // last d
        ull W0 = dup2(wf.x), W1 = dup2(wf.y);
        fma2(acc[0][0], a0.x, W0);  fma2(acc[0][1], a0.x, W1);
        fma2(acc[1][0], a0.y, W0);  fma2(acc[1][1], a0.y, W1);
        fma2(acc[2][0], a1.x, W0);  fma2(acc[2][1], a1.x, W1);
        fma2(acc[3][0], a1.y, W0);  fma2(acc[3][1], a1.y, W1);
        fma2(acc[4][0], a2.x, W0);  fma2(acc[4][1], a2.x, W1);
        fma2(acc[5][0], a2.y, W0);  fma2(acc[5][1], a2.y, W1);
        fma2(acc[6][0], a3.x, W0);  fma2(acc[6][1], a3.x, W1);
        fma2(acc[7][0], a3.y, W0);  fma2(acc[7][1], a3.y, W1);
    }

    // epilogue: rows 16w+2j(+1), cols c0+2L(+1); float2 stores
    float* outp = g_qkv + (long)(p * H + h) * NBOX * DKD;
    int colg = c0 + 2 * L;
    float2 b2 = *(const float2*)&bb[h * DKD + colg];
#pragma unroll
    for (int j = 0; j < 8; ++j) {
        int row = r0 + 2 * j;
        float2 u0 = unpack2(acc[j][0]);   // (C[row][colg],   C[row+1][colg])
        float2 u1 = unpack2(acc[j][1]);   // (C[row][colg+1], C[row+1][colg+1])
        *(float2*)&outp[(row + 0) * DKD + colg] =
            make_float2(u0.x + b2.x, u1.x + b2.y);
        *(float2*)&outp[(row + 1) * DKD + colg] =
            make_float2(u0.y + b2.x, u1.y + b2.y);
    }
}

// ---------------------------------------------------------------------------
// k_attn: 32x128 score tile (f32x2 FMA), + glog, row softmax, partial colsums.
// grid (4, 16), 256 threads.
// ---------------------------------------------------------------------------
__global__ void k_attn() {
    __shared__ __align__(16) ull As2[32][33];
    __shared__ __align__(16) float Bs[32][132];
    __shared__ float psum[8][128];

    int tid = threadIdx.x;
    int mt = blockIdx.x, h = blockIdx.y;
    int m0 = mt * 32;
    int rg = tid >> 5;
    int cg = tid & 31;

    const float* kmat = g_qkv + (long)(0 * H + h) * NBOX * DKD;
    const float* qmat = g_qkv + (long)(1 * H + h) * NBOX * DKD;

    ull acc[4][2] = {};

    for (int kk = 0; kk < DKD; kk += 32) {
        {
            int r = tid >> 3, c4 = tid & 7;
            float4 v = *(const float4*)&kmat[(m0 + r) * DKD + kk + 4 * c4];
            As2[r][4 * c4 + 0] = dup2(v.x);
            As2[r][4 * c4 + 1] = dup2(v.y);
            As2[r][4 * c4 + 2] = dup2(v.z);
            As2[r][4 * c4 + 3] = dup2(v.w);
        }
#pragma unroll
        for (int it = 0; it < 4; ++it) {
            int fidx = tid + 256 * it;
            int n = fidx >> 3, c4 = fidx & 7;
            float4 v = *(const float4*)&qmat[n * DKD + kk + 4 * c4];
            Bs[4 * c4 + 0][n] = v.x;
            Bs[4 * c4 + 1][n] = v.y;
            Bs[4 * c4 + 2][n] = v.z;
            Bs[4 * c4 + 3][n] = v.w;
        }
        __syncthreads();

#pragma unroll
        for (int d = 0; d < 32; ++d) {
            ulonglong2 b = *(ulonglong2*)&Bs[d][4 * cg];
#pragma unroll
            for (int i = 0; i < 4; ++i) {
                ull a = As2[4 * rg + i][d];
                fma2(acc[i][0], a, b.x);
                fma2(acc[i][1], a, b.y);
            }
        }
        __syncthreads();
    }

    const float scale = 0.08838834764831843f;  // 1/sqrt(128)
    float csum[4] = {0.f, 0.f, 0.f, 0.f};
#pragma unroll
    for (int i = 0; i < 4; ++i) {
        int m = m0 + 4 * rg + i;
        float4 gl = *(const float4*)&g_glog[((long)h * NBOX + m) * NBOX + 4 * cg];
        float2 s0 = unpack2(acc[i][0]);
        float2 s1 = unpack2(acc[i][1]);
        float l[4];
        l[0] = s0.x * scale + gl.x;
        l[1] = s0.y * scale + gl.y;
        l[2] = s1.x * scale + gl.z;
        l[3] = s1.y * scale + gl.w;

        float mx = fmaxf(fmaxf(l[0], l[1]), fmaxf(l[2], l[3]));
#pragma unroll
        for (int off = 16; off; off >>= 1)
            mx = fmaxf(mx, __shfl_xor_sync(0xffffffffu, mx, off));

        float e[4], s = 0.f;
#pragma unroll
        for (int j = 0; j < 4; ++j) { e[j] = __expf(l[j] - mx); s += e[j]; }
#pragma unroll
        for (int off = 16; off; off >>= 1)
            s += __shfl_xor_sync(0xffffffffu, s, off);

        float rinv = 1.0f / s;
#pragma unroll
        for (int j = 0; j < 4; ++j) csum[j] += e[j] * rinv;
    }

#pragma unroll
    for (int j = 0; j < 4; ++j) psum[rg][4 * cg + j] = csum[j];
    __syncthreads();

    if (tid < 128) {
        float s = 0.f;
#pragma unroll
        for (int ww = 0; ww < 8; ++ww) s += psum[ww][tid];
        g_partial[(h * 4 + mt) * DKD + tid] = s;
    }
}

// ---------------------------------------------------------------------------
// k_out: out[i, c, d] = v[h,i,k]*colsum[h,k] + f_a[i,d]   (c = h*128+k)
// colsum computed inline from 4 partials. 16.7M float4 streaming stores.
// ---------------------------------------------------------------------------
__global__ void k_out(const float* __restrict__ f_a, float4* __restrict__ out) {
    int idx = blockIdx.x * 512 + threadIdx.x;   // 0..2^24-1
    int d4 = idx & 63;
    int c  = (idx >> 6) & 2047;
    int i  = idx >> 17;
    int h  = c >> 7;
    int k  = c & 127;

    float cs = g_partial[(h * 4 + 0) * DKD + k]
             + g_partial[(h * 4 + 1) * DKD + k]
             + g_partial[(h * 4 + 2) * DKD + k]
             + g_partial[(h * 4 + 3) * DKD + k];
    float s = g_qkv[((long)(2 * H + h) * NBOX + i) * DKD + k] * cs;
    float4 f = ((const float4*)f_a)[i * 64 + d4];
    __stcs(&out[idx], make_float4(s + f.x, s + f.y, s + f.z, s + f.w));
}

// ---------------------------------------------------------------------------
extern "C" void kernel_launch(void* const* d_in, const int* in_sizes, int n_in,
                              void* d_out, int out_size) {
    const float* f_a = (const float*)d_in[0];
    const float* pos = (const float*)d_in[1];
    const float* WG  = (const float*)d_in[2];
    const float* bg  = (const float*)d_in[3];
    const float* WK  = (const float*)d_in[4];
    const float* bk  = (const float*)d_in[5];
    const float* WQ  = (const float*)d_in[6];
    const float* bq  = (const float*)d_in[7];
    const float* WV  = (const float*)d_in[8];
    const float* bv  = (const float*)d_in[9];

    cudaFuncSetAttribute(k_proj, cudaFuncAttributeMaxDynamicSharedMemorySize,
                         DS_TOTAL);

    k_gate<<<256, 256>>>(pos, WG, bg);
    k_proj<<<96, 256, DS_TOTAL>>>(f_a, WK, bk, WQ, bq, WV, bv);
    k_attn<<<dim3(4, 16), 256>>>();
    k_out<<<32768, 512>>>(f_a, (float4*)d_out);
}

// round 14
// speedup vs baseline: 1.0072x; 1.0072x over previous
#include <cuda_runtime.h>

#define H    16
#define NBOX 128
#define DIN  256
#define DKD  128
#define DG   64

typedef unsigned long long ull;

// Scratch (device globals — no allocations allowed)
__device__ float g_glog[H * NBOX * NBOX];      // log(clip(relu(gate))): 1 MB
__device__ float g_qkv[3 * H * NBOX * DKD];    // k,q,v projections: 3 MB
__device__ float g_partial[H * 4 * DKD];       // per-mtile partial colsums

// ---- packed f32x2 helpers (sm_10x FFMA2) ----------------------------------
__device__ __forceinline__ void fma2(ull& acc, ull a, ull b) {
    asm("fma.rn.f32x2 %0, %1, %2, %0;" : "+l"(acc) : "l"(a), "l"(b));
}
__device__ __forceinline__ ull dup2(float a) {
    ull r; asm("mov.b64 %0, {%1, %1};" : "=l"(r) : "f"(a)); return r;
}
__device__ __forceinline__ float2 unpack2(ull v) {
    float2 r; asm("mov.b64 {%0, %1}, %2;" : "=f"(r.x), "=f"(r.y) : "l"(v)); return r;
}

// Dynamic smem (proj):
//   AsT: 256 d x 128 rows f32 (transposed f_a)   = 131072 B
//   Ws2: 256 d x 32 ull (64 cols as f32x2 pairs) =  65536 B
#define DS_TOTAL   (256 * 128 * 4 + 256 * 32 * 8)   // 196608

// ---------------------------------------------------------------------------
// k_gate (standalone, 21 KB STATIC smem -> many blocks/SM, 1 wave):
//   glog[h,m,n] = log(max(pos[m,n,:]·WG[h]+bg[h],1e-6)); 64 pairs/block.
// ---------------------------------------------------------------------------
__global__ void __launch_bounds__(256) k_gate(
        const float* __restrict__ pos,
        const float* __restrict__ WG, const float* __restrict__ bg) {
    __shared__ __align__(16) float pos_s[64][65];
    __shared__ __align__(16) float wg_s[H * DG];

    int tid = threadIdx.x;
    int p0 = blockIdx.x * 64;   // pair base (pair = m*128+n)

    ((float4*)wg_s)[tid] = ((const float4*)WG)[tid];
#pragma unroll
    for (int it = 0; it < 4; ++it) {
        int fidx = tid + 256 * it;
        int pl = fidx >> 4, g4 = fidx & 15;
        float4 v = ((const float4*)pos)[(long)(p0 + pl) * 16 + g4];
        pos_s[pl][4 * g4 + 0] = v.x;
        pos_s[pl][4 * g4 + 1] = v.y;
        pos_s[pl][4 * g4 + 2] = v.z;
        pos_s[pl][4 * g4 + 3] = v.w;
    }
    __syncthreads();

    int row = tid & 63;
    int hg  = tid >> 6;       // heads {hg, hg+4, hg+8, hg+12}
    float acc[4] = {0.f, 0.f, 0.f, 0.f};
#pragma unroll
    for (int g = 0; g < DG; ++g) {
        float pv = pos_s[row][g];
#pragma unroll
        for (int j = 0; j < 4; ++j)
            acc[j] = fmaf(pv, wg_s[(hg + 4 * j) * DG + g], acc[j]);
    }
#pragma unroll
    for (int j = 0; j < 4; ++j) {
        int h = hg + 4 * j;
        float x = acc[j] + bg[h];
        g_glog[h * (NBOX * NBOX) + p0 + row] = __logf(fmaxf(x, 1e-6f));
    }
}

// ---------------------------------------------------------------------------
// k_proj (96 blocks, 256 threads, 192 KB dynamic smem, exactly 1 wave):
//   C(128 x 64) = f_a(128x256) @ W[h,p][:, c0..c0+64) + b
//   A (transposed) + W half-panel staged ONCE; ONE __syncthreads;
//   256-d loop: no barriers, no global loads.
// ---------------------------------------------------------------------------
__global__ void __launch_bounds__(256) k_proj(
        const float* __restrict__ f_a,
        const float* __restrict__ WK, const float* __restrict__ bk,
        const float* __restrict__ WQ, const float* __restrict__ bq,
        const float* __restrict__ WV, const float* __restrict__ bv) {
    extern __shared__ __align__(16) char dsm[];
    int tid = threadIdx.x;
    int w = tid >> 5, L = tid & 31;

    float (*AsT)[128] = (float(*)[128])dsm;                   // [d][row]
    ull   (*Ws2)[32]  = (ull(*)[32])(dsm + 256 * 128 * 4);    // [d][colpair]

    int bid = blockIdx.x;
    int ct = bid & 1;               // col half: cols 64ct .. 64ct+63
    int p  = (bid >> 1) % 3;
    int h  = bid / 6;
    const float* W  = (p == 0) ? WK : ((p == 1) ? WQ : WV);
    const float* bb = (p == 0) ? bk : ((p == 1) ? bq : bv);
    const float* Wh = W + (long)h * DIN * DKD;
    int c0 = 64 * ct;

    // ---- stage A transposed: lane = row (conflict-free STS) ----
#pragma unroll
    for (int it = 0; it < 32; ++it) {
        int idx = w + 8 * it;               // 0..255
        int c4 = idx & 63, rblk = idx >> 6;
        int r = 32 * rblk + L;
        float4 v = *(const float4*)&f_a[r * DIN + 4 * c4];
        AsT[4 * c4 + 0][r] = v.x;
        AsT[4 * c4 + 1][r] = v.y;
        AsT[4 * c4 + 2][r] = v.z;
        AsT[4 * c4 + 3][r] = v.w;
    }
    // ---- stage W half-panel: coalesced LDG.128 + STS.128 ----
#pragma unroll
    for (int it = 0; it < 16; ++it) {
        int fidx = tid + 256 * it;          // 0..4095
        int d = fidx >> 4, q = fidx & 15;
        ulonglong2 v = *(const ulonglong2*)&Wh[d * DKD + c0 + 4 * q];
        *(ulonglong2*)&Ws2[d][2 * q] = v;
    }
    __syncthreads();   // the ONLY barrier

    int r0 = 16 * w;                // warp rows 16w .. 16w+15 (8 ull pairs)
    ull acc[8][2] = {};             // [row-pair j][col i]

    ulonglong2 a0 = *(ulonglong2*)&AsT[0][r0 + 0];
    ulonglong2 a1 = *(ulonglong2*)&AsT[0][r0 + 4];
    ulonglong2 a2 = *(ulonglong2*)&AsT[0][r0 + 8];
    ulonglong2 a3 = *(ulonglong2*)&AsT[0][r0 + 12];
    float2 wf = *(float2*)&Ws2[0][L];   // cols c0+2L, c0+2L+1

#pragma unroll 4
    for (int d = 0; d < DIN - 1; ++d) {
        ulonglong2 n0 = *(ulonglong2*)&AsT[d + 1][r0 + 0];
        ulonglong2 n1 = *(ulonglong2*)&AsT[d + 1][r0 + 4];
        ulonglong2 n2 = *(ulonglong2*)&AsT[d + 1][r0 + 8];
        ulonglong2 n3 = *(ulonglong2*)&AsT[d + 1][r0 + 12];
        float2 nw = *(float2*)&Ws2[d + 1][L];
        ull W0 = dup2(wf.x), W1 = dup2(wf.y);
        fma2(acc[0][0], a0.x, W0);  fma2(acc[0][1], a0.x, W1);
        fma2(acc[1][0], a0.y, W0);  fma2(acc[1][1], a0.y, W1);
        fma2(acc[2][0], a1.x, W0);  fma2(acc[2][1], a1.x, W1);
        fma2(acc[3][0], a1.y, W0);  fma2(acc[3][1], a1.y, W1);
        fma2(acc[4][0], a2.x, W0);  fma2(acc[4][1], a2.x, W1);
        fma2(acc[5][0], a2.y, W0);  fma2(acc[5][1], a2.y, W1);
        fma2(acc[6][0], a3.x, W0);  fma2(acc[6][1], a3.x, W1);
        fma2(acc[7][0], a3.y, W0);  fma2(acc[7][1], a3.y, W1);
        a0 = n0; a1 = n1; a2 = n2; a3 = n3; wf = nw;
    }
    {   // last d
        ull W0 = dup2(wf.x), W1 = dup2(wf.y);
        fma2(acc[0][0], a0.x, W0);  fma2(acc[0][1], a0.x, W1);
        fma2(acc[1][0], a0.y, W0);  fma2(acc[1][1], a0.y, W1);
        fma2(acc[2][0], a1.x, W0);  fma2(acc[2][1], a1.x, W1);
        fma2(acc[3][0], a1.y, W0);  fma2(acc[3][1], a1.y, W1);
        fma2(acc[4][0], a2.x, W0);  fma2(acc[4][1], a2.x, W1);
        fma2(acc[5][0], a2.y, W0);  fma2(acc[5][1], a2.y, W1);
        fma2(acc[6][0], a3.x, W0);  fma2(acc[6][1], a3.x, W1);
        fma2(acc[7][0], a3.y, W0);  fma2(acc[7][1], a3.y, W1);
    }

    float* outp = g_qkv + (long)(p * H + h) * NBOX * DKD;
    int colg = c0 + 2 * L;
    float2 b2 = *(const float2*)&bb[h * DKD + colg];
#pragma unroll
    for (int j = 0; j < 8; ++j) {
        int row = r0 + 2 * j;
        float2 u0 = unpack2(acc[j][0]);
        float2 u1 = unpack2(acc[j][1]);
        *(float2*)&outp[(row + 0) * DKD + colg] =
            make_float2(u0.x + b2.x, u1.x + b2.y);
        *(float2*)&outp[(row + 1) * DKD + colg] =
            make_float2(u0.y + b2.x, u1.y + b2.y);
    }
}

// ---------------------------------------------------------------------------
// k_attn: 32x128 score tile (f32x2 FMA), + glog, row softmax, partial colsums.
// grid (4, 16), 256 threads.
// ---------------------------------------------------------------------------
__global__ void k_attn() {
    __shared__ __align__(16) ull As2[32][33];
    __shared__ __align__(16) float Bs[32][132];
    __shared__ float psum[8][128];

    int tid = threadIdx.x;
    int mt = blockIdx.x, h = blockIdx.y;
    int m0 = mt * 32;
    int rg = tid >> 5;
    int cg = tid & 31;

    const float* kmat = g_qkv + (long)(0 * H + h) * NBOX * DKD;
    const float* qmat = g_qkv + (long)(1 * H + h) * NBOX * DKD;

    ull acc[4][2] = {};

    for (int kk = 0; kk < DKD; kk += 32) {
        {
            int r = tid >> 3, c4 = tid & 7;
            float4 v = *(const float4*)&kmat[(m0 + r) * DKD + kk + 4 * c4];
            As2[r][4 * c4 + 0] = dup2(v.x);
            As2[r][4 * c4 + 1] = dup2(v.y);
            As2[r][4 * c4 + 2] = dup2(v.z);
            As2[r][4 * c4 + 3] = dup2(v.w);
        }
#pragma unroll
        for (int it = 0; it < 4; ++it) {
            int fidx = tid + 256 * it;
            int n = fidx >> 3, c4 = fidx & 7;
            float4 v = *(const float4*)&qmat[n * DKD + kk + 4 * c4];
            Bs[4 * c4 + 0][n] = v.x;
            Bs[4 * c4 + 1][n] = v.y;
            Bs[4 * c4 + 2][n] = v.z;
            Bs[4 * c4 + 3][n] = v.w;
        }
        __syncthreads();

#pragma unroll
        for (int d = 0; d < 32; ++d) {
            ulonglong2 b = *(ulonglong2*)&Bs[d][4 * cg];
#pragma unroll
            for (int i = 0; i < 4; ++i) {
                ull a = As2[4 * rg + i][d];
                fma2(acc[i][0], a, b.x);
                fma2(acc[i][1], a, b.y);
            }
        }
        __syncthreads();
    }

    const float scale = 0.08838834764831843f;  // 1/sqrt(128)
    float csum[4] = {0.f, 0.f, 0.f, 0.f};
#pragma unroll
    for (int i = 0; i < 4; ++i) {
        int m = m0 + 4 * rg + i;
        float4 gl = *(const float4*)&g_glog[((long)h * NBOX + m) * NBOX + 4 * cg];
        float2 s0 = unpack2(acc[i][0]);
        float2 s1 = unpack2(acc[i][1]);
        float l[4];
        l[0] = s0.x * scale + gl.x;
        l[1] = s0.y * scale + gl.y;
        l[2] = s1.x * scale + gl.z;
        l[3] = s1.y * scale + gl.w;

        float mx = fmaxf(fmaxf(l[0], l[1]), fmaxf(l[2], l[3]));
#pragma unroll
        for (int off = 16; off; off >>= 1)
            mx = fmaxf(mx, __shfl_xor_sync(0xffffffffu, mx, off));

        float e[4], s = 0.f;
#pragma unroll
        for (int j = 0; j < 4; ++j) { e[j] = __expf(l[j] - mx); s += e[j]; }
#pragma unroll
        for (int off = 16; off; off >>= 1)
            s += __shfl_xor_sync(0xffffffffu, s, off);

        float rinv = 1.0f / s;
#pragma unroll
        for (int j = 0; j < 4; ++j) csum[j] += e[j] * rinv;
    }

#pragma unroll
    for (int j = 0; j < 4; ++j) psum[rg][4 * cg + j] = csum[j];
    __syncthreads();

    if (tid < 128) {
        float s = 0.f;
#pragma unroll
        for (int ww = 0; ww < 8; ++ww) s += psum[ww][tid];
        g_partial[(h * 4 + mt) * DKD + tid] = s;
    }
}

// ---------------------------------------------------------------------------
// k_out: out[i, c, d] = v[h,i,k]*colsum[h,k] + f_a[i,d]   (c = h*128+k)
// Block = (box i) x (256-channel slice). Stages f_a[i] (1 KB) and the 256
// precomputed sv = v*colsum values in smem ONCE -> L2 sees only the writes.
// Inner loop per thread: LDS(broadcast) + 4 FADD + STG.128, fa in registers.
// ---------------------------------------------------------------------------
__global__ void __launch_bounds__(512) k_out(const float* __restrict__ f_a,
                                             float4* __restrict__ out) {
    __shared__ __align__(16) float4 fa_s[64];
    __shared__ float sv_s[256];

    int tid = threadIdx.x;
    int i  = blockIdx.x >> 3;            // box 0..127
    int c0 = (blockIdx.x & 7) * 256;     // channel slice base

    if (tid < 256) {
        int c = c0 + tid;
        int h = c >> 7, k = c & 127;
        float cs = g_partial[(h * 4 + 0) * DKD + k]
                 + g_partial[(h * 4 + 1) * DKD + k]
                 + g_partial[(h * 4 + 2) * DKD + k]
                 + g_partial[(h * 4 + 3) * DKD + k];
        sv_s[tid] = g_qkv[((long)(2 * H + h) * NBOX + i) * DKD + k] * cs;
    } else if (tid < 320) {
        fa_s[tid - 256] = ((const float4*)f_a)[i * 64 + (tid - 256)];
    }
    __syncthreads();

    int d4 = tid & 63;                   // fixed per thread
    int cgrp = tid >> 6;                 // 0..7 (uniform within each warp)
    float4 fa = fa_s[d4];
    // out float4 index: i*131072 + c*64 + d4
    float4* op = out + (long)i * 131072 + (long)(c0 + 32 * cgrp) * 64 + d4;

#pragma unroll 8
    for (int it = 0; it < 32; ++it) {
        float s = sv_s[32 * cgrp + it];  // warp-uniform LDS broadcast
        __stcs(op + (long)it * 64,
               make_float4(s + fa.x, s + fa.y, s + fa.z, s + fa.w));
    }
}

// ---------------------------------------------------------------------------
extern "C" void kernel_launch(void* const* d_in, const int* in_sizes, int n_in,
                              void* d_out, int out_size) {
    const float* f_a = (const float*)d_in[0];
    const float* pos = (const float*)d_in[1];
    const float* WG  = (const float*)d_in[2];
    const float* bg  = (const float*)d_in[3];
    const float* WK  = (const float*)d_in[4];
    const float* bk  = (const float*)d_in[5];
    const float* WQ  = (const float*)d_in[6];
    const float* bq  = (const float*)d_in[7];
    const float* WV  = (const float*)d_in[8];
    const float* bv  = (const float*)d_in[9];

    cudaFuncSetAttribute(k_proj, cudaFuncAttributeMaxDynamicSharedMemorySize,
                         DS_TOTAL);

    k_gate<<<256, 256>>>(pos, WG, bg);
    k_proj<<<96, 256, DS_TOTAL>>>(f_a, WK, bk, WQ, bq, WV, bv);
    k_attn<<<dim3(4, 16), 256>>>();
    k_out<<<1024, 512>>>(f_a, (float4*)d_out);
}

// round 15
// speedup vs baseline: 1.0510x; 1.0435x over previous
#include <cuda_runtime.h>

#define H    16
#define NBOX 128
#define DIN  256
#define DKD  128
#define DG   64

typedef unsigned long long ull;

// Scratch (device globals — no allocations allowed)
__device__ float g_glog[H * NBOX * NBOX];      // log(clip(relu(gate))): 1 MB
__device__ float g_qkv[3 * H * NBOX * DKD];    // k,q,v projections: 3 MB
__device__ float g_partial[H * 4 * DKD];       // per-mtile partial colsums

// ---- packed f32x2 helpers (sm_10x FFMA2) ----------------------------------
__device__ __forceinline__ void fma2(ull& acc, ull a, ull b) {
    asm("fma.rn.f32x2 %0, %1, %2, %0;" : "+l"(acc) : "l"(a), "l"(b));
}
__device__ __forceinline__ ull dup2(float a) {
    ull r; asm("mov.b64 %0, {%1, %1};" : "=l"(r) : "f"(a)); return r;
}
__device__ __forceinline__ float2 unpack2(ull v) {
    float2 r; asm("mov.b64 {%0, %1}, %2;" : "=f"(r.x), "=f"(r.y) : "l"(v)); return r;
}

// Dynamic smem (proj):
//   AsT: 256 d x 128 rows f32 (transposed f_a)   = 131072 B
//   Ws2: 256 d x 32 ull (64 cols as f32x2 pairs) =  65536 B
#define DS_TOTAL   (256 * 128 * 4 + 256 * 32 * 8)   // 196608

// ---------------------------------------------------------------------------
// k_front (256 threads, 352 blocks, 192 KB dynamic smem, 1 block/SM):
//   blocks [0,96): proj: C(128 x 64) = f_a(128x256) @ W[h,p][:, c0..c0+64) + b
//     A (transposed) + W half-panel staged ONCE; ONE __syncthreads;
//     256-d loop: no barriers, no global loads.
//   blocks [96,352): gate: glog[h,m,n] = log(max(pos[m,n,:]·WG[h]+bg[h],1e-6))
//     (gate blocks fill the 52 SMs proj doesn't use; fused launch measured
//      equal to proj alone in round 12.)
// ---------------------------------------------------------------------------
__global__ void __launch_bounds__(256) k_front(
        const float* __restrict__ f_a,
        const float* __restrict__ pos,
        const float* __restrict__ WG, const float* __restrict__ bg,
        const float* __restrict__ WK, const float* __restrict__ bk,
        const float* __restrict__ WQ, const float* __restrict__ bq,
        const float* __restrict__ WV, const float* __restrict__ bv) {
    extern __shared__ __align__(16) char dsm[];
    int tid = threadIdx.x;
    int w = tid >> 5, L = tid & 31;

    if (blockIdx.x < 96) {
        // ---------------- proj path ----------------
        float (*AsT)[128] = (float(*)[128])dsm;                   // [d][row]
        ull   (*Ws2)[32]  = (ull(*)[32])(dsm + 256 * 128 * 4);    // [d][colpair]

        int bid = blockIdx.x;
        int ct = bid & 1;               // col half: cols 64ct .. 64ct+63
        int p  = (bid >> 1) % 3;
        int h  = bid / 6;
        const float* W  = (p == 0) ? WK : ((p == 1) ? WQ : WV);
        const float* bb = (p == 0) ? bk : ((p == 1) ? bq : bv);
        const float* Wh = W + (long)h * DIN * DKD;
        int c0 = 64 * ct;

        // ---- stage A transposed ----
#pragma unroll
        for (int it = 0; it < 32; ++it) {
            int idx = w + 8 * it;               // 0..255
            int c4 = idx & 63, rblk = idx >> 6;
            int r = 32 * rblk + L;
            float4 v = *(const float4*)&f_a[r * DIN + 4 * c4];
            AsT[4 * c4 + 0][r] = v.x;
            AsT[4 * c4 + 1][r] = v.y;
            AsT[4 * c4 + 2][r] = v.z;
            AsT[4 * c4 + 3][r] = v.w;
        }
        // ---- stage W half-panel: coalesced LDG.128 + STS.128 ----
#pragma unroll
        for (int it = 0; it < 16; ++it) {
            int fidx = tid + 256 * it;          // 0..4095
            int d = fidx >> 4, q = fidx & 15;
            ulonglong2 v = *(const ulonglong2*)&Wh[d * DKD + c0 + 4 * q];
            *(ulonglong2*)&Ws2[d][2 * q] = v;
        }
        __syncthreads();   // the ONLY barrier

        int r0 = 16 * w;                // warp rows 16w .. 16w+15 (8 ull pairs)
        ull acc[8][2] = {};             // [row-pair j][col i]

        ulonglong2 a0 = *(ulonglong2*)&AsT[0][r0 + 0];
        ulonglong2 a1 = *(ulonglong2*)&AsT[0][r0 + 4];
        ulonglong2 a2 = *(ulonglong2*)&AsT[0][r0 + 8];
        ulonglong2 a3 = *(ulonglong2*)&AsT[0][r0 + 12];
        float2 wf = *(float2*)&Ws2[0][L];   // cols c0+2L, c0+2L+1

#pragma unroll 4
        for (int d = 0; d < DIN - 1; ++d) {
            ulonglong2 n0 = *(ulonglong2*)&AsT[d + 1][r0 + 0];
            ulonglong2 n1 = *(ulonglong2*)&AsT[d + 1][r0 + 4];
            ulonglong2 n2 = *(ulonglong2*)&AsT[d + 1][r0 + 8];
            ulonglong2 n3 = *(ulonglong2*)&AsT[d + 1][r0 + 12];
            float2 nw = *(float2*)&Ws2[d + 1][L];
            ull W0 = dup2(wf.x), W1 = dup2(wf.y);
            fma2(acc[0][0], a0.x, W0);  fma2(acc[0][1], a0.x, W1);
            fma2(acc[1][0], a0.y, W0);  fma2(acc[1][1], a0.y, W1);
            fma2(acc[2][0], a1.x, W0);  fma2(acc[2][1], a1.x, W1);
            fma2(acc[3][0], a1.y, W0);  fma2(acc[3][1], a1.y, W1);
            fma2(acc[4][0], a2.x, W0);  fma2(acc[4][1], a2.x, W1);
            fma2(acc[5][0], a2.y, W0);  fma2(acc[5][1], a2.y, W1);
            fma2(acc[6][0], a3.x, W0);  fma2(acc[6][1], a3.x, W1);
            fma2(acc[7][0], a3.y, W0);  fma2(acc[7][1], a3.y, W1);
            a0 = n0; a1 = n1; a2 = n2; a3 = n3; wf = nw;
        }
        {   // last d
            ull W0 = dup2(wf.x), W1 = dup2(wf.y);
            fma2(acc[0][0], a0.x, W0);  fma2(acc[0][1], a0.x, W1);
            fma2(acc[1][0], a0.y, W0);  fma2(acc[1][1], a0.y, W1);
            fma2(acc[2][0], a1.x, W0);  fma2(acc[2][1], a1.x, W1);
            fma2(acc[3][0], a1.y, W0);  fma2(acc[3][1], a1.y, W1);
            fma2(acc[4][0], a2.x, W0);  fma2(acc[4][1], a2.x, W1);
            fma2(acc[5][0], a2.y, W0);  fma2(acc[5][1], a2.y, W1);
            fma2(acc[6][0], a3.x, W0);  fma2(acc[6][1], a3.x, W1);
            fma2(acc[7][0], a3.y, W0);  fma2(acc[7][1], a3.y, W1);
        }

        float* outp = g_qkv + (long)(p * H + h) * NBOX * DKD;
        int colg = c0 + 2 * L;
        float2 b2 = *(const float2*)&bb[h * DKD + colg];
#pragma unroll
        for (int j = 0; j < 8; ++j) {
            int row = r0 + 2 * j;
            float2 u0 = unpack2(acc[j][0]);
            float2 u1 = unpack2(acc[j][1]);
            *(float2*)&outp[(row + 0) * DKD + colg] =
                make_float2(u0.x + b2.x, u1.x + b2.y);
            *(float2*)&outp[(row + 1) * DKD + colg] =
                make_float2(u0.y + b2.x, u1.y + b2.y);
        }
    } else {
        // ---------------- gate path (64 pairs / block) ----------------
        float (*pos_s)[65] = (float(*)[65])dsm;              // 64x65 = 16640 B
        float* wg_s = (float*)(dsm + 64 * 65 * 4);           // 16x64 =  4096 B

        int p0 = (blockIdx.x - 96) * 64;   // pair base (pair = m*128+n)

        ((float4*)wg_s)[tid] = ((const float4*)WG)[tid];
#pragma unroll
        for (int it = 0; it < 4; ++it) {
            int fidx = tid + 256 * it;
            int pl = fidx >> 4, g4 = fidx & 15;
            float4 v = ((const float4*)pos)[(long)(p0 + pl) * 16 + g4];
            pos_s[pl][4 * g4 + 0] = v.x;
            pos_s[pl][4 * g4 + 1] = v.y;
            pos_s[pl][4 * g4 + 2] = v.z;
            pos_s[pl][4 * g4 + 3] = v.w;
        }
        __syncthreads();

        int row = tid & 63;
        int hg  = tid >> 6;       // heads {hg, hg+4, hg+8, hg+12}
        float acc[4] = {0.f, 0.f, 0.f, 0.f};
#pragma unroll
        for (int g = 0; g < DG; ++g) {
            float pv = pos_s[row][g];
#pragma unroll
            for (int j = 0; j < 4; ++j)
                acc[j] = fmaf(pv, wg_s[(hg + 4 * j) * DG + g], acc[j]);
        }
#pragma unroll
        for (int j = 0; j < 4; ++j) {
            int h = hg + 4 * j;
            float x = acc[j] + bg[h];
            g_glog[h * (NBOX * NBOX) + p0 + row] = __logf(fmaxf(x, 1e-6f));
        }
    }
}

// ---------------------------------------------------------------------------
// k_attn: 32x128 score tile (f32x2 FMA), + glog, row softmax, partial colsums.
// grid (4, 16), 256 threads.
// ---------------------------------------------------------------------------
__global__ void k_attn() {
    __shared__ __align__(16) ull As2[32][33];
    __shared__ __align__(16) float Bs[32][132];
    __shared__ float psum[8][128];

    int tid = threadIdx.x;
    int mt = blockIdx.x, h = blockIdx.y;
    int m0 = mt * 32;
    int rg = tid >> 5;
    int cg = tid & 31;

    const float* kmat = g_qkv + (long)(0 * H + h) * NBOX * DKD;
    const float* qmat = g_qkv + (long)(1 * H + h) * NBOX * DKD;

    ull acc[4][2] = {};

    for (int kk = 0; kk < DKD; kk += 32) {
        {
            int r = tid >> 3, c4 = tid & 7;
            float4 v = *(const float4*)&kmat[(m0 + r) * DKD + kk + 4 * c4];
            As2[r][4 * c4 + 0] = dup2(v.x);
            As2[r][4 * c4 + 1] = dup2(v.y);
            As2[r][4 * c4 + 2] = dup2(v.z);
            As2[r][4 * c4 + 3] = dup2(v.w);
        }
#pragma unroll
        for (int it = 0; it < 4; ++it) {
            int fidx = tid + 256 * it;
            int n = fidx >> 3, c4 = fidx & 7;
            float4 v = *(const float4*)&qmat[n * DKD + kk + 4 * c4];
            Bs[4 * c4 + 0][n] = v.x;
            Bs[4 * c4 + 1][n] = v.y;
            Bs[4 * c4 + 2][n] = v.z;
            Bs[4 * c4 + 3][n] = v.w;
        }
        __syncthreads();

#pragma unroll
        for (int d = 0; d < 32; ++d) {
            ulonglong2 b = *(ulonglong2*)&Bs[d][4 * cg];
#pragma unroll
            for (int i = 0; i < 4; ++i) {
                ull a = As2[4 * rg + i][d];
                fma2(acc[i][0], a, b.x);
                fma2(acc[i][1], a, b.y);
            }
        }
        __syncthreads();
    }

    const float scale = 0.08838834764831843f;  // 1/sqrt(128)
    float csum[4] = {0.f, 0.f, 0.f, 0.f};
#pragma unroll
    for (int i = 0; i < 4; ++i) {
        int m = m0 + 4 * rg + i;
        float4 gl = *(const float4*)&g_glog[((long)h * NBOX + m) * NBOX + 4 * cg];
        float2 s0 = unpack2(acc[i][0]);
        float2 s1 = unpack2(acc[i][1]);
        float l[4];
        l[0] = s0.x * scale + gl.x;
        l[1] = s0.y * scale + gl.y;
        l[2] = s1.x * scale + gl.z;
        l[3] = s1.y * scale + gl.w;

        float mx = fmaxf(fmaxf(l[0], l[1]), fmaxf(l[2], l[3]));
#pragma unroll
        for (int off = 16; off; off >>= 1)
            mx = fmaxf(mx, __shfl_xor_sync(0xffffffffu, mx, off));

        float e[4], s = 0.f;
#pragma unroll
        for (int j = 0; j < 4; ++j) { e[j] = __expf(l[j] - mx); s += e[j]; }
#pragma unroll
        for (int off = 16; off; off >>= 1)
            s += __shfl_xor_sync(0xffffffffu, s, off);

        float rinv = 1.0f / s;
#pragma unroll
        for (int j = 0; j < 4; ++j) csum[j] += e[j] * rinv;
    }

#pragma unroll
    for (int j = 0; j < 4; ++j) psum[rg][4 * cg + j] = csum[j];
    __syncthreads();

    if (tid < 128) {
        float s = 0.f;
#pragma unroll
        for (int ww = 0; ww < 8; ++ww) s += psum[ww][tid];
        g_partial[(h * 4 + mt) * DKD + tid] = s;
    }
}

// ---------------------------------------------------------------------------
// k_out: out[i, c, d] = v[h,i,k]*colsum[h,k] + f_a[i,d]   (c = h*128+k)
// Block = (box i) x (256-channel slice). Stages f_a[i] (1 KB) and the 256
// precomputed sv = v*colsum values in smem ONCE -> L2 sees only the writes.
// ---------------------------------------------------------------------------
__global__ void __launch_bounds__(512) k_out(const float* __restrict__ f_a,
                                             float4* __restrict__ out) {
    __shared__ __align__(16) float4 fa_s[64];
    __shared__ float sv_s[256];

    int tid = threadIdx.x;
    int i  = blockIdx.x >> 3;            // box 0..127
    int c0 = (blockIdx.x & 7) * 256;     // channel slice base

    if (tid < 256) {
        int c = c0 + tid;
        int h = c >> 7, k = c & 127;
        float cs = g_partial[(h * 4 + 0) * DKD + k]
                 + g_partial[(h * 4 + 1) * DKD + k]
                 + g_partial[(h * 4 + 2) * DKD + k]
                 + g_partial[(h * 4 + 3) * DKD + k];
        sv_s[tid] = g_qkv[((long)(2 * H + h) * NBOX + i) * DKD + k] * cs;
    } else if (tid < 320) {
        fa_s[tid - 256] = ((const float4*)f_a)[i * 64 + (tid - 256)];
    }
    __syncthreads();

    int d4 = tid & 63;                   // fixed per thread
    int cgrp = tid >> 6;                 // 0..7 (uniform within each warp)
    float4 fa = fa_s[d4];
    float4* op = out + (long)i * 131072 + (long)(c0 + 32 * cgrp) * 64 + d4;

#pragma unroll 8
    for (int it = 0; it < 32; ++it) {
        float s = sv_s[32 * cgrp + it];  // warp-uniform LDS broadcast
        __stcs(op + (long)it * 64,
               make_float4(s + fa.x, s + fa.y, s + fa.z, s + fa.w));
    }
}

// ---------------------------------------------------------------------------
extern "C" void kernel_launch(void* const* d_in, const int* in_sizes, int n_in,
                              void* d_out, int out_size) {
    const float* f_a = (const float*)d_in[0];
    const float* pos = (const float*)d_in[1];
    const float* WG  = (const float*)d_in[2];
    const float* bg  = (const float*)d_in[3];
    const float* WK  = (const float*)d_in[4];
    const float* bk  = (const float*)d_in[5];
    const float* WQ  = (const float*)d_in[6];
    const float* bq  = (const float*)d_in[7];
    const float* WV  = (const float*)d_in[8];
    const float* bv  = (const float*)d_in[9];

    cudaFuncSetAttribute(k_front, cudaFuncAttributeMaxDynamicSharedMemorySize,
                         DS_TOTAL);

    k_front<<<352, 256, DS_TOTAL>>>(f_a, pos, WG, bg, WK, bk, WQ, bq, WV, bv);
    k_attn<<<dim3(4, 16), 256>>>();
    k_out<<<1024, 512>>>(f_a, (float4*)d_out);
}

// round 16
// speedup vs baseline: 1.0566x; 1.0053x over previous
#include <cuda_runtime.h>

#define H    16
#define NBOX 128
#define DIN  256
#define DKD  128
#define DG   64

typedef unsigned long long ull;

// Scratch (device globals — no allocations allowed)
__device__ float g_glog[H * NBOX * NBOX];      // log(clip(relu(gate))): 1 MB
__device__ float g_qkv[3 * H * NBOX * DKD];    // k,q,v projections: 3 MB
__device__ float g_partial[H * 4 * DKD];       // per-mtile partial colsums

// Intra-launch dependency flags (zero-init; reset in-launch by last consumer)
__device__ unsigned g_done[H];      // proj blocks done per head (6 each)
__device__ unsigned g_gate_cnt;     // gate blocks done (256)
__device__ unsigned g_attn_fin;     // attn blocks finished (64) -> reset

// ---- packed f32x2 helpers (sm_10x FFMA2) ----------------------------------
__device__ __forceinline__ void fma2(ull& acc, ull a, ull b) {
    asm("fma.rn.f32x2 %0, %1, %2, %0;" : "+l"(acc) : "l"(a), "l"(b));
}
__device__ __forceinline__ ull dup2(float a) {
    ull r; asm("mov.b64 %0, {%1, %1};" : "=l"(r) : "f"(a)); return r;
}
__device__ __forceinline__ float2 unpack2(ull v) {
    float2 r; asm("mov.b64 {%0, %1}, %2;" : "=f"(r.x), "=f"(r.y) : "l"(v)); return r;
}

// Dynamic smem (proj):
//   AsT: 256 d x 128 rows f32 (transposed f_a)   = 131072 B
//   Ws2: 256 d x 32 ull (64 cols as f32x2 pairs) =  65536 B
#define DS_TOTAL   (256 * 128 * 4 + 256 * 32 * 8)   // 196608

// ---------------------------------------------------------------------------
// k_front (256 threads, 416 blocks, 192 KB dynamic smem, 1 block/SM):
//   blocks [0,96):    proj: C(128x64) = f_a @ W[h,p][:,c0..c0+64) + b
//                     (round-15 proven path; releases g_done[h] when done)
//   blocks [96,352):  gate (releases g_gate_cnt)
//   blocks [352,416): attn (mt,h): spins until gate==256 && g_done[h]==6,
//                     then 32x128 score tile + softmax + partial colsums.
//   Deadlock-free: only 64 blocks spin (< 148 SMs); producers never wait.
// ---------------------------------------------------------------------------
__global__ void __launch_bounds__(256) k_front(
        const float* __restrict__ f_a,
        const float* __restrict__ pos,
        const float* __restrict__ WG, const float* __restrict__ bg,
        const float* __restrict__ WK, const float* __restrict__ bk,
        const float* __restrict__ WQ, const float* __restrict__ bq,
        const float* __restrict__ WV, const float* __restrict__ bv) {
    extern __shared__ __align__(16) char dsm[];
    int tid = threadIdx.x;
    int w = tid >> 5, L = tid & 31;

    if (blockIdx.x < 96) {
        // ---------------- proj path ----------------
        float (*AsT)[128] = (float(*)[128])dsm;                   // [d][row]
        ull   (*Ws2)[32]  = (ull(*)[32])(dsm + 256 * 128 * 4);    // [d][colpair]

        int bid = blockIdx.x;
        int ct = bid & 1;
        int p  = (bid >> 1) % 3;
        int h  = bid / 6;
        const float* W  = (p == 0) ? WK : ((p == 1) ? WQ : WV);
        const float* bb = (p == 0) ? bk : ((p == 1) ? bq : bv);
        const float* Wh = W + (long)h * DIN * DKD;
        int c0 = 64 * ct;

#pragma unroll
        for (int it = 0; it < 32; ++it) {
            int idx = w + 8 * it;
            int c4 = idx & 63, rblk = idx >> 6;
            int r = 32 * rblk + L;
            float4 v = *(const float4*)&f_a[r * DIN + 4 * c4];
            AsT[4 * c4 + 0][r] = v.x;
            AsT[4 * c4 + 1][r] = v.y;
            AsT[4 * c4 + 2][r] = v.z;
            AsT[4 * c4 + 3][r] = v.w;
        }
#pragma unroll
        for (int it = 0; it < 16; ++it) {
            int fidx = tid + 256 * it;
            int d = fidx >> 4, q = fidx & 15;
            ulonglong2 v = *(const ulonglong2*)&Wh[d * DKD + c0 + 4 * q];
            *(ulonglong2*)&Ws2[d][2 * q] = v;
        }
        __syncthreads();

        int r0 = 16 * w;
        ull acc[8][2] = {};

        ulonglong2 a0 = *(ulonglong2*)&AsT[0][r0 + 0];
        ulonglong2 a1 = *(ulonglong2*)&AsT[0][r0 + 4];
        ulonglong2 a2 = *(ulonglong2*)&AsT[0][r0 + 8];
        ulonglong2 a3 = *(ulonglong2*)&AsT[0][r0 + 12];
        float2 wf = *(float2*)&Ws2[0][L];

#pragma unroll 4
        for (int d = 0; d < DIN - 1; ++d) {
            ulonglong2 n0 = *(ulonglong2*)&AsT[d + 1][r0 + 0];
            ulonglong2 n1 = *(ulonglong2*)&AsT[d + 1][r0 + 4];
            ulonglong2 n2 = *(ulonglong2*)&AsT[d + 1][r0 + 8];
            ulonglong2 n3 = *(ulonglong2*)&AsT[d + 1][r0 + 12];
            float2 nw = *(float2*)&Ws2[d + 1][L];
            ull W0 = dup2(wf.x), W1 = dup2(wf.y);
            fma2(acc[0][0], a0.x, W0);  fma2(acc[0][1], a0.x, W1);
            fma2(acc[1][0], a0.y, W0);  fma2(acc[1][1], a0.y, W1);
            fma2(acc[2][0], a1.x, W0);  fma2(acc[2][1], a1.x, W1);
            fma2(acc[3][0], a1.y, W0);  fma2(acc[3][1], a1.y, W1);
            fma2(acc[4][0], a2.x, W0);  fma2(acc[4][1], a2.x, W1);
            fma2(acc[5][0], a2.y, W0);  fma2(acc[5][1], a2.y, W1);
            fma2(acc[6][0], a3.x, W0);  fma2(acc[6][1], a3.x, W1);
            fma2(acc[7][0], a3.y, W0);  fma2(acc[7][1], a3.y, W1);
            a0 = n0; a1 = n1; a2 = n2; a3 = n3; wf = nw;
        }
        {   // last d
            ull W0 = dup2(wf.x), W1 = dup2(wf.y);
            fma2(acc[0][0], a0.x, W0);  fma2(acc[0][1], a0.x, W1);
            fma2(acc[1][0], a0.y, W0);  fma2(acc[1][1], a0.y, W1);
            fma2(acc[2][0], a1.x, W0);  fma2(acc[2][1], a1.x, W1);
            fma2(acc[3][0], a1.y, W0);  fma2(acc[3][1], a1.y, W1);
            fma2(acc[4][0], a2.x, W0);  fma2(acc[4][1], a2.x, W1);
            fma2(acc[5][0], a2.y, W0);  fma2(acc[5][1], a2.y, W1);
            fma2(acc[6][0], a3.x, W0);  fma2(acc[6][1], a3.x, W1);
            fma2(acc[7][0], a3.y, W0);  fma2(acc[7][1], a3.y, W1);
        }

        float* outp = g_qkv + (long)(p * H + h) * NBOX * DKD;
        int colg = c0 + 2 * L;
        float2 b2 = *(const float2*)&bb[h * DKD + colg];
#pragma unroll
        for (int j = 0; j < 8; ++j) {
            int row = r0 + 2 * j;
            float2 u0 = unpack2(acc[j][0]);
            float2 u1 = unpack2(acc[j][1]);
            *(float2*)&outp[(row + 0) * DKD + colg] =
                make_float2(u0.x + b2.x, u1.x + b2.y);
            *(float2*)&outp[(row + 1) * DKD + colg] =
                make_float2(u0.y + b2.x, u1.y + b2.y);
        }

        // release: this (h,p,ct) tile of g_qkv is globally visible
        __syncthreads();
        if (tid == 0) { __threadfence(); atomicAdd(&g_done[h], 1u); }
    } else if (blockIdx.x < 352) {
        // ---------------- gate path (64 pairs / block) ----------------
        float (*pos_s)[65] = (float(*)[65])dsm;
        float* wg_s = (float*)(dsm + 64 * 65 * 4);

        int p0 = (blockIdx.x - 96) * 64;

        ((float4*)wg_s)[tid] = ((const float4*)WG)[tid];
#pragma unroll
        for (int it = 0; it < 4; ++it) {
            int fidx = tid + 256 * it;
            int pl = fidx >> 4, g4 = fidx & 15;
            float4 v = ((const float4*)pos)[(long)(p0 + pl) * 16 + g4];
            pos_s[pl][4 * g4 + 0] = v.x;
            pos_s[pl][4 * g4 + 1] = v.y;
            pos_s[pl][4 * g4 + 2] = v.z;
            pos_s[pl][4 * g4 + 3] = v.w;
        }
        __syncthreads();

        int row = tid & 63;
        int hg  = tid >> 6;
        float acc[4] = {0.f, 0.f, 0.f, 0.f};
#pragma unroll
        for (int g = 0; g < DG; ++g) {
            float pv = pos_s[row][g];
#pragma unroll
            for (int j = 0; j < 4; ++j)
                acc[j] = fmaf(pv, wg_s[(hg + 4 * j) * DG + g], acc[j]);
        }
#pragma unroll
        for (int j = 0; j < 4; ++j) {
            int h = hg + 4 * j;
            float x = acc[j] + bg[h];
            g_glog[h * (NBOX * NBOX) + p0 + row] = __logf(fmaxf(x, 1e-6f));
        }

        __syncthreads();
        if (tid == 0) { __threadfence(); atomicAdd(&g_gate_cnt, 1u); }
    } else {
        // ---------------- attn path (spins on proj+gate flags) ----------
        ull   (*As2)[33]  = (ull(*)[33])dsm;                       // 8448 B
        float (*Bs)[132]  = (float(*)[132])(dsm + 32 * 33 * 8);    // 16896 B
        float (*psum)[128] = (float(*)[128])(dsm + 32 * 33 * 8 + 32 * 132 * 4);

        int a  = blockIdx.x - 352;
        int mt = a & 3;
        int h  = a >> 2;
        int m0 = mt * 32;
        int rg = tid >> 5;
        int cg = tid & 31;

        if (tid == 0) {
            while (atomicAdd(&g_gate_cnt, 0u) < 256u) __nanosleep(64);
            while (atomicAdd(&g_done[h], 0u) < 6u)    __nanosleep(64);
            __threadfence();
        }
        __syncthreads();

        const float* kmat = g_qkv + (long)(0 * H + h) * NBOX * DKD;
        const float* qmat = g_qkv + (long)(1 * H + h) * NBOX * DKD;

        ull acc[4][2] = {};

        for (int kk = 0; kk < DKD; kk += 32) {
            {
                int r = tid >> 3, c4 = tid & 7;
                float4 v = *(const float4*)&kmat[(m0 + r) * DKD + kk + 4 * c4];
                As2[r][4 * c4 + 0] = dup2(v.x);
                As2[r][4 * c4 + 1] = dup2(v.y);
                As2[r][4 * c4 + 2] = dup2(v.z);
                As2[r][4 * c4 + 3] = dup2(v.w);
            }
#pragma unroll
            for (int it = 0; it < 4; ++it) {
                int fidx = tid + 256 * it;
                int n = fidx >> 3, c4 = fidx & 7;
                float4 v = *(const float4*)&qmat[n * DKD + kk + 4 * c4];
                Bs[4 * c4 + 0][n] = v.x;
                Bs[4 * c4 + 1][n] = v.y;
                Bs[4 * c4 + 2][n] = v.z;
                Bs[4 * c4 + 3][n] = v.w;
            }
            __syncthreads();

#pragma unroll
            for (int d = 0; d < 32; ++d) {
                ulonglong2 b = *(ulonglong2*)&Bs[d][4 * cg];
#pragma unroll
                for (int i = 0; i < 4; ++i) {
                    ull av = As2[4 * rg + i][d];
                    fma2(acc[i][0], av, b.x);
                    fma2(acc[i][1], av, b.y);
                }
            }
            __syncthreads();
        }

        const float scale = 0.08838834764831843f;  // 1/sqrt(128)
        float csum[4] = {0.f, 0.f, 0.f, 0.f};
#pragma unroll
        for (int i = 0; i < 4; ++i) {
            int m = m0 + 4 * rg + i;
            float4 gl = *(const float4*)&g_glog[((long)h * NBOX + m) * NBOX + 4 * cg];
            float2 s0 = unpack2(acc[i][0]);
            float2 s1 = unpack2(acc[i][1]);
            float l[4];
            l[0] = s0.x * scale + gl.x;
            l[1] = s0.y * scale + gl.y;
            l[2] = s1.x * scale + gl.z;
            l[3] = s1.y * scale + gl.w;

            float mx = fmaxf(fmaxf(l[0], l[1]), fmaxf(l[2], l[3]));
#pragma unroll
            for (int off = 16; off; off >>= 1)
                mx = fmaxf(mx, __shfl_xor_sync(0xffffffffu, mx, off));

            float e[4], s = 0.f;
#pragma unroll
            for (int j = 0; j < 4; ++j) { e[j] = __expf(l[j] - mx); s += e[j]; }
#pragma unroll
            for (int off = 16; off; off >>= 1)
                s += __shfl_xor_sync(0xffffffffu, s, off);

            float rinv = 1.0f / s;
#pragma unroll
            for (int j = 0; j < 4; ++j) csum[j] += e[j] * rinv;
        }

#pragma unroll
        for (int j = 0; j < 4; ++j) psum[rg][4 * cg + j] = csum[j];
        __syncthreads();

        if (tid < 128) {
            float s = 0.f;
#pragma unroll
            for (int ww = 0; ww < 8; ++ww) s += psum[ww][tid];
            g_partial[(h * 4 + mt) * DKD + tid] = s;
        }

        // last attn block globally resets flags for the next graph replay
        __syncthreads();
        if (tid == 0) {
            unsigned f = atomicAdd(&g_attn_fin, 1u);
            if (f == 63u) {
#pragma unroll
                for (int i = 0; i < H; ++i) g_done[i] = 0u;
                g_gate_cnt = 0u;
                g_attn_fin = 0u;
            }
        }
    }
}

// ---------------------------------------------------------------------------
// k_out: out[i, c, d] = v[h,i,k]*colsum[h,k] + f_a[i,d]   (c = h*128+k)
// Block = (box i) x (256-channel slice). Stages f_a[i] and sv = v*colsum in
// smem ONCE -> L2 sees only the writes. (Round-14 proven: 40.9us, DRAM 65%.)
// ---------------------------------------------------------------------------
__global__ void __launch_bounds__(512) k_out(const float* __restrict__ f_a,
                                             float4* __restrict__ out) {
    __shared__ __align__(16) float4 fa_s[64];
    __shared__ float sv_s[256];

    int tid = threadIdx.x;
    int i  = blockIdx.x >> 3;            // box 0..127
    int c0 = (blockIdx.x & 7) * 256;     // channel slice base

    if (tid < 256) {
        int c = c0 + tid;
        int h = c >> 7, k = c & 127;
        float cs = g_partial[(h * 4 + 0) * DKD + k]
                 + g_partial[(h * 4 + 1) * DKD + k]
                 + g_partial[(h * 4 + 2) * DKD + k]
                 + g_partial[(h * 4 + 3) * DKD + k];
        sv_s[tid] = g_qkv[((long)(2 * H + h) * NBOX + i) * DKD + k] * cs;
    } else if (tid < 320) {
        fa_s[tid - 256] = ((const float4*)f_a)[i * 64 + (tid - 256)];
    }
    __syncthreads();

    int d4 = tid & 63;                   // fixed per thread
    int cgrp = tid >> 6;                 // 0..7 (uniform within each warp)
    float4 fa = fa_s[d4];
    float4* op = out + (long)i * 131072 + (long)(c0 + 32 * cgrp) * 64 + d4;

#pragma unroll 8
    for (int it = 0; it < 32; ++it) {
        float s = sv_s[32 * cgrp + it];  // warp-uniform LDS broadcast
        __stcs(op + (long)it * 64,
               make_float4(s + fa.x, s + fa.y, s + fa.z, s + fa.w));
    }
}

// ---------------------------------------------------------------------------
extern "C" void kernel_launch(void* const* d_in, const int* in_sizes, int n_in,
                              void* d_out, int out_size) {
    const float* f_a = (const float*)d_in[0];
    const float* pos = (const float*)d_in[1];
    const float* WG  = (const float*)d_in[2];
    const float* bg  = (const float*)d_in[3];
    const float* WK  = (const float*)d_in[4];
    const float* bk  = (const float*)d_in[5];
    const float* WQ  = (const float*)d_in[6];
    const float* bq  = (const float*)d_in[7];
    const float* WV  = (const float*)d_in[8];
    const float* bv  = (const float*)d_in[9];

    cudaFuncSetAttribute(k_front, cudaFuncAttributeMaxDynamicSharedMemorySize,
                         DS_TOTAL);

    k_front<<<416, 256, DS_TOTAL>>>(f_a, pos, WG, bg, WK, bk, WQ, bq, WV, bv);
    k_out<<<1024, 512>>>(f_a, (float4*)d_out);
}